// round 8
// baseline (speedup 1.0000x reference)
#include <cuda_runtime.h>
#include <cstdint>

// Problem shape
#define BDIM   8192
#define DDIM   2048
#define NUNITS 2048
#define KW     64          // 2048 bits = 64 u32 words per row

// N-split: popc handles nblk 0..11 (cols 0..1535), imma handles nblk 12..15
#define POPC_NBLKS 12

// ---- imma tiling (role B) ----
#define TILE_M 128
#define TILE_N 128
#define KC     128
#define KITERS (DDIM / KC)          // 16
#define TILE_BYTES (TILE_M * KC)    // 16384
#define STAGE_BYTES (2 * TILE_BYTES)
#define HYB_SMEM 65536              // popc: 2*64*128*4 = 64KB ; imma: 2 stages * 32KB = 64KB

// Scratch (allocation-free rule: __device__ globals)
__device__ __align__(128) uint32_t g_Abits[(size_t)(BDIM / 128) * KW * 128];   // 2 MB
__device__ __align__(128) uint32_t g_Bbits[(size_t)(NUNITS / 128) * KW * 128]; // 512 KB
__device__ __align__(128) int8_t   g_A8[(size_t)BDIM * DDIM];                  // 16 MB
__device__ __align__(128) int8_t   g_B8[(size_t)NUNITS * DDIM];                // 4 MB

// ============================ PTX helpers ============================

__device__ __forceinline__ uint32_t smem_u32(const void* p) {
    uint32_t a;
    asm("{ .reg .u64 t; cvta.to.shared.u64 t, %1; cvt.u32.u64 %0, t; }" : "=r"(a) : "l"(p));
    return a;
}
__device__ __forceinline__ void cp_async16(uint32_t dst, const void* src) {
    asm volatile("cp.async.cg.shared.global [%0], [%1], 16;" :: "r"(dst), "l"(src) : "memory");
}
#define CP_COMMIT() asm volatile("cp.async.commit_group;" ::: "memory")
#define CP_WAIT(n)  asm volatile("cp.async.wait_group %0;" :: "n"(n) : "memory")

__device__ __forceinline__ void ldm_x4(uint32_t* r, uint32_t addr) {
    asm volatile("ldmatrix.sync.aligned.m8n8.x4.shared.b16 {%0,%1,%2,%3}, [%4];"
                 : "=r"(r[0]), "=r"(r[1]), "=r"(r[2]), "=r"(r[3]) : "r"(addr));
}
__device__ __forceinline__ void mma_s8(int* d, const uint32_t* a, const uint32_t* b) {
    asm volatile(
        "mma.sync.aligned.m16n8k32.row.col.s32.s8.s8.s32 "
        "{%0,%1,%2,%3}, {%4,%5,%6,%7}, {%8,%9}, {%0,%1,%2,%3};"
        : "+r"(d[0]), "+r"(d[1]), "+r"(d[2]), "+r"(d[3])
        : "r"(a[0]), "r"(a[1]), "r"(a[2]), "r"(a[3]), "r"(b[0]), "r"(b[1]));
}
__device__ __forceinline__ uint32_t swz(int r, int c) {
    return (uint32_t)(r * 128 + ((c ^ (r & 7)) << 4));
}

// ============================ Fused pack kernels ============================

// inputs [B, D] fp32 -> bits (ballot) AND s8 (+1/-1), one read of A
__global__ void pack_a_fused(const float* __restrict__ in,
                             uint32_t* __restrict__ bits, int8_t* __restrict__ a8) {
    int lane = threadIdx.x & 31;
    int warp = (blockIdx.x * blockDim.x + threadIdx.x) >> 5;
    float v[8];
#pragma unroll
    for (int s = 0; s < 8; s++) {
        int w = warp * 8 + s;
        int m = w >> 6, j = w & 63;
        v[s] = in[(size_t)m * DDIM + j * 32 + lane];
    }
#pragma unroll
    for (int s = 0; s < 8; s++) {
        int w = warp * 8 + s;
        int m = w >> 6, j = w & 63;
        bool neg = (v[s] < 0.0f);
        uint32_t word = __ballot_sync(0xFFFFFFFFu, neg);
        a8[(size_t)m * DDIM + j * 32 + lane] = neg ? (int8_t)-1 : (int8_t)1;
        if (lane == 0)
            bits[(size_t)(m >> 7) * (KW * 128) + j * 128 + (m & 127)] = word;
    }
}

// kernel [D, UNITS] fp32 -> transposed bits AND s8 [N, K], one read of kernel
__global__ void pack_b_fused(const float* __restrict__ kern,
                             uint32_t* __restrict__ bits, int8_t* __restrict__ b8) {
    __shared__ uint8_t tile[32][33];          // [k][n], 1 = negative
    int n0 = blockIdx.x * 32;
    int k0 = blockIdx.y * 32;
    int tx = threadIdx.x, ty = threadIdx.y;   // (32, 8)
#pragma unroll
    for (int s = 0; s < 4; s++) {
        int kk = ty + s * 8;
        float v = kern[(size_t)(k0 + kk) * NUNITS + n0 + tx];
        tile[kk][tx] = (v < 0.0f) ? 1 : 0;
    }
    __syncthreads();
    int tid = ty * 32 + tx;
    int wid5 = tid >> 5;
    int lane = tx;
    // bits: ballot over k-dimension
#pragma unroll
    for (int s = 0; s < 4; s++) {
        int nl = wid5 * 4 + s;
        uint32_t word = __ballot_sync(0xFFFFFFFFu, tile[lane][nl] != 0);
        if (lane == 0) {
            int n = n0 + nl;
            bits[(size_t)(n >> 7) * (KW * 128) + blockIdx.y * 128 + (n & 127)] = word;
        }
    }
    // s8: 4 bytes per thread
    {
        int nloc = tid >> 3;
        int kgrp = tid & 7;
        uint32_t w = 0;
#pragma unroll
        for (int b = 0; b < 4; b++) {
            uint32_t byte = tile[kgrp * 4 + b][nloc] ? 0xFFu : 0x01u;
            w |= byte << (8 * b);
        }
        *reinterpret_cast<uint32_t*>(b8 + (size_t)(n0 + nloc) * DDIM + k0 + kgrp * 4) = w;
    }
}

// ============================ Hybrid GEMM ============================

__device__ __forceinline__ void popc_role(
    const uint32_t* __restrict__ Ab, const uint32_t* __restrict__ Bb,
    const float* __restrict__ bias, float* __restrict__ out, char* smraw)
{
    uint32_t* Asm = (uint32_t*)smraw;
    uint32_t* Bsm = Asm + KW * 128;

    const int tid = threadIdx.x;
    const int nblk = blockIdx.x, mblk = blockIdx.y;

    {
        const uint4* gA = (const uint4*)(Ab + (size_t)mblk * (KW * 128));
        const uint4* gB = (const uint4*)(Bb + (size_t)nblk * (KW * 128));
        uint4* sA = (uint4*)Asm;
        uint4* sB = (uint4*)Bsm;
#pragma unroll
        for (int i = 0; i < 8; i++) {
            sA[tid + i * 256] = gA[tid + i * 256];
            sB[tid + i * 256] = gB[tid + i * 256];
        }
    }
    __syncthreads();

    const int tx = tid & 15;
    const int ty = tid >> 4;

    int acc[8][8];
#pragma unroll
    for (int i = 0; i < 8; i++)
#pragma unroll
        for (int k = 0; k < 8; k++) acc[i][k] = 0;

#pragma unroll 2
    for (int jg = 0; jg < 20; jg++) {
        uint32_t a0[8], a1[8], a2[8], b0[8], b1[8], b2[8];
        const uint32_t* Ap = &Asm[(jg * 3) * 128 + ty * 8];
        const uint32_t* Bp = &Bsm[(jg * 3) * 128 + tx * 8];
        *(uint4*)&a0[0] = *(const uint4*)&Ap[0];   *(uint4*)&a0[4] = *(const uint4*)&Ap[4];
        *(uint4*)&a1[0] = *(const uint4*)&Ap[128]; *(uint4*)&a1[4] = *(const uint4*)&Ap[132];
        *(uint4*)&a2[0] = *(const uint4*)&Ap[256]; *(uint4*)&a2[4] = *(const uint4*)&Ap[260];
        *(uint4*)&b0[0] = *(const uint4*)&Bp[0];   *(uint4*)&b0[4] = *(const uint4*)&Bp[4];
        *(uint4*)&b1[0] = *(const uint4*)&Bp[128]; *(uint4*)&b1[4] = *(const uint4*)&Bp[132];
        *(uint4*)&b2[0] = *(const uint4*)&Bp[256]; *(uint4*)&b2[4] = *(const uint4*)&Bp[260];
#pragma unroll
        for (int mi = 0; mi < 8; mi++) {
#pragma unroll
            for (int ni = 0; ni < 8; ni++) {
                uint32_t x0 = a0[mi] ^ b0[ni];
                uint32_t x1 = a1[mi] ^ b1[ni];
                uint32_t x2 = a2[mi] ^ b2[ni];
                uint32_t s = x0 ^ x1 ^ x2;
                uint32_t c = (x0 & x1) | (x2 & (x0 | x1));
                acc[mi][ni] += __popc(s) + 2 * __popc(c);
            }
        }
    }
    {   // raw tail: words 60..63
        uint32_t a0[8], a1[8], a2[8], a3[8], b0[8], b1[8], b2[8], b3[8];
        const uint32_t* Ap = &Asm[60 * 128 + ty * 8];
        const uint32_t* Bp = &Bsm[60 * 128 + tx * 8];
        *(uint4*)&a0[0] = *(const uint4*)&Ap[0];   *(uint4*)&a0[4] = *(const uint4*)&Ap[4];
        *(uint4*)&a1[0] = *(const uint4*)&Ap[128]; *(uint4*)&a1[4] = *(const uint4*)&Ap[132];
        *(uint4*)&a2[0] = *(const uint4*)&Ap[256]; *(uint4*)&a2[4] = *(const uint4*)&Ap[260];
        *(uint4*)&a3[0] = *(const uint4*)&Ap[384]; *(uint4*)&a3[4] = *(const uint4*)&Ap[388];
        *(uint4*)&b0[0] = *(const uint4*)&Bp[0];   *(uint4*)&b0[4] = *(const uint4*)&Bp[4];
        *(uint4*)&b1[0] = *(const uint4*)&Bp[128]; *(uint4*)&b1[4] = *(const uint4*)&Bp[132];
        *(uint4*)&b2[0] = *(const uint4*)&Bp[256]; *(uint4*)&b2[4] = *(const uint4*)&Bp[260];
        *(uint4*)&b3[0] = *(const uint4*)&Bp[384]; *(uint4*)&b3[4] = *(const uint4*)&Bp[388];
#pragma unroll
        for (int mi = 0; mi < 8; mi++) {
#pragma unroll
            for (int ni = 0; ni < 8; ni++) {
                int p0 = __popc(a0[mi] ^ b0[ni]);
                int p1 = __popc(a1[mi] ^ b1[ni]);
                int p2 = __popc(a2[mi] ^ b2[ni]);
                int p3 = __popc(a3[mi] ^ b3[ni]);
                acc[mi][ni] += (p0 + p1) + (p2 + p3);
            }
        }
    }

    const int n0 = nblk * 128 + tx * 8;
    float bl[8];
    *(float4*)&bl[0] = *(const float4*)&bias[n0];
    *(float4*)&bl[4] = *(const float4*)&bias[n0 + 4];
#pragma unroll
    for (int i = 0; i < 8; i++) bl[i] += 2048.0f;

#pragma unroll
    for (int mi = 0; mi < 8; mi++) {
        size_t row = (size_t)(mblk * 128 + ty * 8 + mi) * NUNITS + n0;
        float4 v0, v1;
        v0.x = fmaf(-2.0f, (float)acc[mi][0], bl[0]);
        v0.y = fmaf(-2.0f, (float)acc[mi][1], bl[1]);
        v0.z = fmaf(-2.0f, (float)acc[mi][2], bl[2]);
        v0.w = fmaf(-2.0f, (float)acc[mi][3], bl[3]);
        v1.x = fmaf(-2.0f, (float)acc[mi][4], bl[4]);
        v1.y = fmaf(-2.0f, (float)acc[mi][5], bl[5]);
        v1.z = fmaf(-2.0f, (float)acc[mi][6], bl[6]);
        v1.w = fmaf(-2.0f, (float)acc[mi][7], bl[7]);
        *(float4*)&out[row]     = v0;
        *(float4*)&out[row + 4] = v1;
    }
}

__device__ __forceinline__ void imma_role(
    const int8_t* __restrict__ A, const int8_t* __restrict__ Bt,
    const float* __restrict__ bias, float* __restrict__ out, char* smraw)
{
    const uint32_t sb = smem_u32(smraw);
    const int tid  = threadIdx.x;
    const int wid  = tid >> 5, lane = tid & 31;
    const int wm   = wid & 3;
    const int wn   = wid >> 2;
    const int m0   = blockIdx.y * TILE_M;
    const int n0   = blockIdx.x * TILE_N;      // blockIdx.x in [12,16)

    int acc[2][8][4];
#pragma unroll
    for (int i = 0; i < 2; i++)
#pragma unroll
        for (int j = 0; j < 8; j++)
#pragma unroll
            for (int k = 0; k < 4; k++) acc[i][j][k] = 0;

    const int cr = tid >> 3;
    const int cc = tid & 7;

    // prologue: stage 0
    {
        uint32_t sa = sb, sbuf = sb + TILE_BYTES;
#pragma unroll
        for (int p = 0; p < 4; p++) {
            int r = cr + p * 32;
            cp_async16(sa + swz(r, cc),   A  + (size_t)(m0 + r) * DDIM + cc * 16);
            cp_async16(sbuf + swz(r, cc), Bt + (size_t)(n0 + r) * DDIM + cc * 16);
        }
        CP_COMMIT();
    }

    const int a_lrow = lane & 15;
    const int a_csel = lane >> 4;
    const int b_lrow = (lane & 7) + ((lane >> 4) << 3);
    const int b_csel = (lane >> 3) & 1;

    for (int it = 0; it < KITERS; it++) {
        if (it + 1 < KITERS) {
            int sn = (it + 1) & 1;
            uint32_t na = sb + sn * STAGE_BYTES;
            uint32_t nb = na + TILE_BYTES;
            int ks = (it + 1) * KC;
#pragma unroll
            for (int p = 0; p < 4; p++) {
                int r = cr + p * 32;
                cp_async16(na + swz(r, cc), A  + (size_t)(m0 + r) * DDIM + ks + cc * 16);
                cp_async16(nb + swz(r, cc), Bt + (size_t)(n0 + r) * DDIM + ks + cc * 16);
            }
            CP_COMMIT();
            CP_WAIT(1);
        } else {
            CP_WAIT(0);
        }
        __syncthreads();

        uint32_t sa = sb + (it & 1) * STAGE_BYTES;
        uint32_t sbuf = sa + TILE_BYTES;
#pragma unroll
        for (int ks = 0; ks < KC / 32; ks++) {
            uint32_t afr[2][4];
#pragma unroll
            for (int mf = 0; mf < 2; mf++) {
                int row = wm * 32 + mf * 16 + a_lrow;
                int ch = ks * 2 + a_csel;
                ldm_x4(afr[mf], sa + swz(row, ch));
            }
            uint32_t bfr[8][2];
#pragma unroll
            for (int np = 0; np < 4; np++) {
                int row = wn * 64 + np * 16 + b_lrow;
                int ch = ks * 2 + b_csel;
                uint32_t r4[4];
                ldm_x4(r4, sbuf + swz(row, ch));
                bfr[2 * np][0] = r4[0]; bfr[2 * np][1] = r4[1];
                bfr[2 * np + 1][0] = r4[2]; bfr[2 * np + 1][1] = r4[3];
            }
#pragma unroll
            for (int mf = 0; mf < 2; mf++)
#pragma unroll
                for (int nf = 0; nf < 8; nf++)
                    mma_s8(acc[mf][nf], afr[mf], bfr[nf]);
        }
        __syncthreads();
    }

    const int row_base = m0 + wm * 32 + (lane >> 2);
    const int col_base = n0 + wn * 64 + 2 * (lane & 3);
#pragma unroll
    for (int nf = 0; nf < 8; nf++) {
        int c = col_base + nf * 8;
        float b0 = bias[c], b1 = bias[c + 1];
#pragma unroll
        for (int mf = 0; mf < 2; mf++) {
            int r = row_base + mf * 16;
            float2 v0 = make_float2((float)acc[mf][nf][0] + b0, (float)acc[mf][nf][1] + b1);
            *reinterpret_cast<float2*>(&out[(size_t)r * NUNITS + c]) = v0;
            float2 v1 = make_float2((float)acc[mf][nf][2] + b0, (float)acc[mf][nf][3] + b1);
            *reinterpret_cast<float2*>(&out[(size_t)(r + 8) * NUNITS + c]) = v1;
        }
    }
}

__global__ void __launch_bounds__(256) hybrid_gemm(
    const uint32_t* __restrict__ Ab, const uint32_t* __restrict__ Bb,
    const int8_t* __restrict__ A8, const int8_t* __restrict__ B8,
    const float* __restrict__ bias, float* __restrict__ out)
{
    extern __shared__ char smraw[];
    if (blockIdx.x < POPC_NBLKS)
        popc_role(Ab, Bb, bias, out, smraw);
    else
        imma_role(A8, B8, bias, out, smraw);
}

// ============================ Host ============================

extern "C" void kernel_launch(void* const* d_in, const int* in_sizes, int n_in,
                              void* d_out, int out_size) {
    const float* inputs = (const float*)d_in[0];
    const float* kern   = (const float*)d_in[1];
    const float* bias   = (const float*)d_in[2];
    float* out = (float*)d_out;

    void *pAb = nullptr, *pBb = nullptr, *pA8 = nullptr, *pB8 = nullptr;
    cudaGetSymbolAddress(&pAb, g_Abits);
    cudaGetSymbolAddress(&pBb, g_Bbits);
    cudaGetSymbolAddress(&pA8, g_A8);
    cudaGetSymbolAddress(&pB8, g_B8);

    // 1) fused pack A (bits + s8), one read of inputs
    {
        int words = BDIM * KW;
        int blocks = words / (8 * 8);          // 8192
        pack_a_fused<<<blocks, 256>>>(inputs, (uint32_t*)pAb, (int8_t*)pA8);
    }
    // 2) fused pack B (bits + s8 transposed)
    {
        dim3 tb(32, 8), tg(NUNITS / 32, DDIM / 32);
        pack_b_fused<<<tg, tb>>>(kern, (uint32_t*)pBb, (int8_t*)pB8);
    }
    // 3) hybrid GEMM: popc CTAs (x<12) + imma CTAs (x>=12)
    cudaFuncSetAttribute(hybrid_gemm, cudaFuncAttributeMaxDynamicSharedMemorySize, HYB_SMEM);
    dim3 grid(NUNITS / 128, BDIM / 128);       // (16, 64)
    hybrid_gemm<<<grid, 256, HYB_SMEM>>>((const uint32_t*)pAb, (const uint32_t*)pBb,
                                         (const int8_t*)pA8, (const int8_t*)pB8, bias, out);
}

// round 9
// speedup vs baseline: 1.1624x; 1.1624x over previous
#include <cuda_runtime.h>
#include <cstdint>

// Problem shape
#define BDIM   8192
#define DDIM   2048
#define NUNITS 2048
#define KW     64          // 2048 bits = 64 u32 words

// CTA tile 128x128: popc warps 0-5 -> cols 0..95 ; imma warps 6-7 -> cols 96..127
#define KC     128
#define KITERS (DDIM / KC)              // 16
#define SM_ABITS    0                   // 64*128*4  = 32768
#define SM_BBITS    32768               // 64*96*4   = 24576
#define SM_IMMA     57344               // 2 stages * 20480
#define IMMA_STAGE  20480               // A8 16384 + B8 4096
#define HYB_SMEM    98304               // 96 KB -> 2 CTAs/SM

// Scratch (allocation-free rule: __device__ globals)
__device__ __align__(128) uint32_t g_Abits[(size_t)(BDIM / 128) * KW * 128];   // 2 MB
__device__ __align__(128) uint32_t g_Bbits[(size_t)(NUNITS / 128) * KW * 128]; // 512 KB
__device__ __align__(128) int8_t   g_A8[(size_t)BDIM * DDIM];                  // 16 MB
__device__ __align__(128) int8_t   g_B8[(size_t)NUNITS * DDIM];                // 4 MB (only n%128>=96 used)

// ============================ PTX helpers ============================

__device__ __forceinline__ uint32_t smem_u32(const void* p) {
    uint32_t a;
    asm("{ .reg .u64 t; cvta.to.shared.u64 t, %1; cvt.u32.u64 %0, t; }" : "=r"(a) : "l"(p));
    return a;
}
__device__ __forceinline__ void cp_async16(uint32_t dst, const void* src) {
    asm volatile("cp.async.cg.shared.global [%0], [%1], 16;" :: "r"(dst), "l"(src) : "memory");
}
#define CP_COMMIT() asm volatile("cp.async.commit_group;" ::: "memory")
#define CP_WAIT(n)  asm volatile("cp.async.wait_group %0;" :: "n"(n) : "memory")
#define BAR_SYNC(id, cnt) asm volatile("bar.sync %0, %1;" :: "r"(id), "r"(cnt) : "memory")

__device__ __forceinline__ void ldm_x4(uint32_t* r, uint32_t addr) {
    asm volatile("ldmatrix.sync.aligned.m8n8.x4.shared.b16 {%0,%1,%2,%3}, [%4];"
                 : "=r"(r[0]), "=r"(r[1]), "=r"(r[2]), "=r"(r[3]) : "r"(addr));
}
__device__ __forceinline__ void mma_s8(int* d, const uint32_t* a, const uint32_t* b) {
    asm volatile(
        "mma.sync.aligned.m16n8k32.row.col.s32.s8.s8.s32 "
        "{%0,%1,%2,%3}, {%4,%5,%6,%7}, {%8,%9}, {%0,%1,%2,%3};"
        : "+r"(d[0]), "+r"(d[1]), "+r"(d[2]), "+r"(d[3])
        : "r"(a[0]), "r"(a[1]), "r"(a[2]), "r"(a[3]), "r"(b[0]), "r"(b[1]));
}
__device__ __forceinline__ uint32_t swz(int r, int c) {
    return (uint32_t)(r * 128 + ((c ^ (r & 7)) << 4));
}

// ============================ Fused pack kernels ============================

__global__ void pack_a_fused(const float* __restrict__ in,
                             uint32_t* __restrict__ bits, int8_t* __restrict__ a8) {
    int lane = threadIdx.x & 31;
    int warp = (blockIdx.x * blockDim.x + threadIdx.x) >> 5;
    float v[8];
#pragma unroll
    for (int s = 0; s < 8; s++) {
        int w = warp * 8 + s;
        int m = w >> 6, j = w & 63;
        v[s] = in[(size_t)m * DDIM + j * 32 + lane];
    }
#pragma unroll
    for (int s = 0; s < 8; s++) {
        int w = warp * 8 + s;
        int m = w >> 6, j = w & 63;
        bool neg = (v[s] < 0.0f);
        uint32_t word = __ballot_sync(0xFFFFFFFFu, neg);
        a8[(size_t)m * DDIM + j * 32 + lane] = neg ? (int8_t)-1 : (int8_t)1;
        if (lane == 0)
            bits[(size_t)(m >> 7) * (KW * 128) + j * 128 + (m & 127)] = word;
    }
}

__global__ void pack_b_fused(const float* __restrict__ kern,
                             uint32_t* __restrict__ bits, int8_t* __restrict__ b8) {
    __shared__ uint8_t tile[32][33];          // [k][n], 1 = negative
    int n0 = blockIdx.x * 32;
    int k0 = blockIdx.y * 32;
    int tx = threadIdx.x, ty = threadIdx.y;   // (32, 8)
#pragma unroll
    for (int s = 0; s < 4; s++) {
        int kk = ty + s * 8;
        float v = kern[(size_t)(k0 + kk) * NUNITS + n0 + tx];
        tile[kk][tx] = (v < 0.0f) ? 1 : 0;
    }
    __syncthreads();
    int tid = ty * 32 + tx;
    int wid5 = tid >> 5;
    int lane = tx;
#pragma unroll
    for (int s = 0; s < 4; s++) {
        int nl = wid5 * 4 + s;
        uint32_t word = __ballot_sync(0xFFFFFFFFu, tile[lane][nl] != 0);
        if (lane == 0) {
            int n = n0 + nl;
            bits[(size_t)(n >> 7) * (KW * 128) + blockIdx.y * 128 + (n & 127)] = word;
        }
    }
    // s8 only needed for columns with n%128 >= 96 (imma slice)
    if ((blockIdx.x & 3) == 3) {
        int nloc = tid >> 3;
        int kgrp = tid & 7;
        uint32_t w = 0;
#pragma unroll
        for (int b = 0; b < 4; b++) {
            uint32_t byte = tile[kgrp * 4 + b][nloc] ? 0xFFu : 0x01u;
            w |= byte << (8 * b);
        }
        *reinterpret_cast<uint32_t*>(b8 + (size_t)(n0 + nloc) * DDIM + k0 + kgrp * 4) = w;
    }
}

// ============================ Hybrid GEMM (warp-specialized) ============================

__device__ __forceinline__ void popc_role(
    const uint32_t* __restrict__ Ab, const uint32_t* __restrict__ Bb,
    const float* __restrict__ bias, float* __restrict__ out, char* smraw)
{
    uint32_t* Asm = (uint32_t*)(smraw + SM_ABITS);
    uint32_t* Bsm = (uint32_t*)(smraw + SM_BBITS);

    const int tid = threadIdx.x;              // 0..191
    const int nblk = blockIdx.x, mblk = blockIdx.y;

    // cooperative bit-tile load (192 threads)
    {
        const uint4* gA = (const uint4*)(Ab + (size_t)mblk * (KW * 128));
        uint4* sA = (uint4*)Asm;
        for (int i = tid; i < 2048; i += 192) sA[i] = gA[i];
        const uint4* gB = (const uint4*)(Bb + (size_t)nblk * (KW * 128));
        uint4* sB = (uint4*)Bsm;
        for (int i = tid; i < 1536; i += 192) {     // 96 cols = 24 uint4 per word-row
            int j = i / 24, c4 = i % 24;
            sB[i] = gB[j * 32 + c4];
        }
    }
    BAR_SYNC(1, 192);

    const int tx = tid % 12;                  // n sub-block (12 x 8 = 96 cols)
    const int ty = tid / 12;                  // m sub-block (16 x 8 = 128 rows)

    int acc[8][8];
#pragma unroll
    for (int i = 0; i < 8; i++)
#pragma unroll
        for (int k = 0; k < 8; k++) acc[i][k] = 0;

#pragma unroll 2
    for (int jg = 0; jg < 20; jg++) {
        uint32_t a0[8], a1[8], a2[8], b0[8], b1[8], b2[8];
        const uint32_t* Ap = &Asm[(jg * 3) * 128 + ty * 8];
        const uint32_t* Bp = &Bsm[(jg * 3) * 96 + tx * 8];
        *(uint4*)&a0[0] = *(const uint4*)&Ap[0];   *(uint4*)&a0[4] = *(const uint4*)&Ap[4];
        *(uint4*)&a1[0] = *(const uint4*)&Ap[128]; *(uint4*)&a1[4] = *(const uint4*)&Ap[132];
        *(uint4*)&a2[0] = *(const uint4*)&Ap[256]; *(uint4*)&a2[4] = *(const uint4*)&Ap[260];
        *(uint4*)&b0[0] = *(const uint4*)&Bp[0];   *(uint4*)&b0[4] = *(const uint4*)&Bp[4];
        *(uint4*)&b1[0] = *(const uint4*)&Bp[96];  *(uint4*)&b1[4] = *(const uint4*)&Bp[100];
        *(uint4*)&b2[0] = *(const uint4*)&Bp[192]; *(uint4*)&b2[4] = *(const uint4*)&Bp[196];
#pragma unroll
        for (int mi = 0; mi < 8; mi++) {
#pragma unroll
            for (int ni = 0; ni < 8; ni++) {
                uint32_t x0 = a0[mi] ^ b0[ni];
                uint32_t x1 = a1[mi] ^ b1[ni];
                uint32_t x2 = a2[mi] ^ b2[ni];
                uint32_t s = x0 ^ x1 ^ x2;
                uint32_t c = (x0 & x1) | (x2 & (x0 | x1));
                acc[mi][ni] += __popc(s) + 2 * __popc(c);
            }
        }
    }
    {   // raw tail: words 60..63
        uint32_t a0[8], a1[8], a2[8], a3[8], b0[8], b1[8], b2[8], b3[8];
        const uint32_t* Ap = &Asm[60 * 128 + ty * 8];
        const uint32_t* Bp = &Bsm[60 * 96 + tx * 8];
        *(uint4*)&a0[0] = *(const uint4*)&Ap[0];   *(uint4*)&a0[4] = *(const uint4*)&Ap[4];
        *(uint4*)&a1[0] = *(const uint4*)&Ap[128]; *(uint4*)&a1[4] = *(const uint4*)&Ap[132];
        *(uint4*)&a2[0] = *(const uint4*)&Ap[256]; *(uint4*)&a2[4] = *(const uint4*)&Ap[260];
        *(uint4*)&a3[0] = *(const uint4*)&Ap[384]; *(uint4*)&a3[4] = *(const uint4*)&Ap[388];
        *(uint4*)&b0[0] = *(const uint4*)&Bp[0];   *(uint4*)&b0[4] = *(const uint4*)&Bp[4];
        *(uint4*)&b1[0] = *(const uint4*)&Bp[96];  *(uint4*)&b1[4] = *(const uint4*)&Bp[100];
        *(uint4*)&b2[0] = *(const uint4*)&Bp[192]; *(uint4*)&b2[4] = *(const uint4*)&Bp[196];
        *(uint4*)&b3[0] = *(const uint4*)&Bp[288]; *(uint4*)&b3[4] = *(const uint4*)&Bp[292];
#pragma unroll
        for (int mi = 0; mi < 8; mi++) {
#pragma unroll
            for (int ni = 0; ni < 8; ni++) {
                int p0 = __popc(a0[mi] ^ b0[ni]);
                int p1 = __popc(a1[mi] ^ b1[ni]);
                int p2 = __popc(a2[mi] ^ b2[ni]);
                int p3 = __popc(a3[mi] ^ b3[ni]);
                acc[mi][ni] += (p0 + p1) + (p2 + p3);
            }
        }
    }

    const int n0 = nblk * 128 + tx * 8;
    float bl[8];
    *(float4*)&bl[0] = *(const float4*)&bias[n0];
    *(float4*)&bl[4] = *(const float4*)&bias[n0 + 4];
#pragma unroll
    for (int i = 0; i < 8; i++) bl[i] += 2048.0f;

#pragma unroll
    for (int mi = 0; mi < 8; mi++) {
        size_t row = (size_t)(mblk * 128 + ty * 8 + mi) * NUNITS + n0;
        float4 v0, v1;
        v0.x = fmaf(-2.0f, (float)acc[mi][0], bl[0]);
        v0.y = fmaf(-2.0f, (float)acc[mi][1], bl[1]);
        v0.z = fmaf(-2.0f, (float)acc[mi][2], bl[2]);
        v0.w = fmaf(-2.0f, (float)acc[mi][3], bl[3]);
        v1.x = fmaf(-2.0f, (float)acc[mi][4], bl[4]);
        v1.y = fmaf(-2.0f, (float)acc[mi][5], bl[5]);
        v1.z = fmaf(-2.0f, (float)acc[mi][6], bl[6]);
        v1.w = fmaf(-2.0f, (float)acc[mi][7], bl[7]);
        *(float4*)&out[row]     = v0;
        *(float4*)&out[row + 4] = v1;
    }
}

__device__ __forceinline__ void imma_role(
    const int8_t* __restrict__ A, const int8_t* __restrict__ Bt,
    const float* __restrict__ bias, float* __restrict__ out, char* smraw)
{
    const uint32_t sb = smem_u32(smraw) + SM_IMMA;
    const int tid2 = threadIdx.x - 192;       // 0..63
    const int lane = threadIdx.x & 31;
    const int wl   = tid2 >> 5;               // 0,1 -> 16 cols each
    const int m0   = blockIdx.y * 128;
    const int nb   = blockIdx.x * 128 + 96;   // imma slice base

    int acc[8][2][4];
#pragma unroll
    for (int i = 0; i < 8; i++)
#pragma unroll
        for (int j = 0; j < 2; j++)
#pragma unroll
            for (int k = 0; k < 4; k++) acc[i][j][k] = 0;

    const int cr = tid2 >> 3;                 // 0..7
    const int cc = tid2 & 7;

    // prologue: stage 0
    {
        uint32_t sa = sb, sbuf = sb + 16384;
#pragma unroll
        for (int p = 0; p < 16; p++) {
            int r = cr + p * 8;
            cp_async16(sa + swz(r, cc), A + (size_t)(m0 + r) * DDIM + cc * 16);
        }
#pragma unroll
        for (int p = 0; p < 4; p++) {
            int r = cr + p * 8;
            cp_async16(sbuf + swz(r, cc), Bt + (size_t)(nb + r) * DDIM + cc * 16);
        }
        CP_COMMIT();
    }

    const int a_lrow = lane & 15;
    const int a_csel = lane >> 4;
    const int b_lrow = (lane & 7) + ((lane >> 4) << 3);
    const int b_csel = (lane >> 3) & 1;

    for (int it = 0; it < KITERS; it++) {
        if (it + 1 < KITERS) {
            uint32_t na = sb + ((it + 1) & 1) * IMMA_STAGE;
            uint32_t nbuf = na + 16384;
            int ks = (it + 1) * KC;
#pragma unroll
            for (int p = 0; p < 16; p++) {
                int r = cr + p * 8;
                cp_async16(na + swz(r, cc), A + (size_t)(m0 + r) * DDIM + ks + cc * 16);
            }
#pragma unroll
            for (int p = 0; p < 4; p++) {
                int r = cr + p * 8;
                cp_async16(nbuf + swz(r, cc), Bt + (size_t)(nb + r) * DDIM + ks + cc * 16);
            }
            CP_COMMIT();
            CP_WAIT(1);
        } else {
            CP_WAIT(0);
        }
        BAR_SYNC(2, 64);

        uint32_t sa = sb + (it & 1) * IMMA_STAGE;
        uint32_t sbuf = sa + 16384;
#pragma unroll
        for (int ks = 0; ks < KC / 32; ks++) {
            uint32_t bfr[4];
            ldm_x4(bfr, sbuf + swz(wl * 16 + b_lrow, ks * 2 + b_csel));
#pragma unroll
            for (int mf = 0; mf < 8; mf++) {
                uint32_t afr[4];
                ldm_x4(afr, sa + swz(mf * 16 + a_lrow, ks * 2 + a_csel));
                mma_s8(acc[mf][0], afr, &bfr[0]);
                mma_s8(acc[mf][1], afr, &bfr[2]);
            }
        }
        BAR_SYNC(2, 64);   // all 64 done with stage before it gets overwritten
    }

    const int row_base = m0 + (lane >> 2);
    const int col_base = nb + wl * 16 + 2 * (lane & 3);
#pragma unroll
    for (int nf = 0; nf < 2; nf++) {
        int c = col_base + nf * 8;
        float b0 = bias[c], b1 = bias[c + 1];
#pragma unroll
        for (int mf = 0; mf < 8; mf++) {
            int r = row_base + mf * 16;
            float2 v0 = make_float2((float)acc[mf][nf][0] + b0, (float)acc[mf][nf][1] + b1);
            *reinterpret_cast<float2*>(&out[(size_t)r * NUNITS + c]) = v0;
            float2 v1 = make_float2((float)acc[mf][nf][2] + b0, (float)acc[mf][nf][3] + b1);
            *reinterpret_cast<float2*>(&out[(size_t)(r + 8) * NUNITS + c]) = v1;
        }
    }
}

__global__ void __launch_bounds__(256, 2) hybrid_gemm(
    const uint32_t* __restrict__ Ab, const uint32_t* __restrict__ Bb,
    const int8_t* __restrict__ A8, const int8_t* __restrict__ B8,
    const float* __restrict__ bias, float* __restrict__ out)
{
    extern __shared__ char smraw[];
    if (threadIdx.x < 192)
        popc_role(Ab, Bb, bias, out, smraw);
    else
        imma_role(A8, B8, bias, out, smraw);
}

// ============================ Host ============================

extern "C" void kernel_launch(void* const* d_in, const int* in_sizes, int n_in,
                              void* d_out, int out_size) {
    const float* inputs = (const float*)d_in[0];
    const float* kern   = (const float*)d_in[1];
    const float* bias   = (const float*)d_in[2];
    float* out = (float*)d_out;

    void *pAb = nullptr, *pBb = nullptr, *pA8 = nullptr, *pB8 = nullptr;
    cudaGetSymbolAddress(&pAb, g_Abits);
    cudaGetSymbolAddress(&pBb, g_Bbits);
    cudaGetSymbolAddress(&pA8, g_A8);
    cudaGetSymbolAddress(&pB8, g_B8);

    {
        int words = BDIM * KW;
        int blocks = words / (8 * 8);          // 8192
        pack_a_fused<<<blocks, 256>>>(inputs, (uint32_t*)pAb, (int8_t*)pA8);
    }
    {
        dim3 tb(32, 8), tg(NUNITS / 32, DDIM / 32);
        pack_b_fused<<<tg, tb>>>(kern, (uint32_t*)pBb, (int8_t*)pB8);
    }
    cudaFuncSetAttribute(hybrid_gemm, cudaFuncAttributeMaxDynamicSharedMemorySize, HYB_SMEM);
    dim3 grid(NUNITS / 128, BDIM / 128);       // (16, 64)
    hybrid_gemm<<<grid, 256, HYB_SMEM>>>((const uint32_t*)pAb, (const uint32_t*)pBb,
                                         (const int8_t*)pA8, (const int8_t*)pB8, bias, out);
}

// round 10
// speedup vs baseline: 1.3531x; 1.1641x over previous
#include <cuda_runtime.h>
#include <cstdint>

#define BDIM   8192
#define DDIM   2048
#define NUNITS 2048
#define WB     56               // bit words per row (k < 1792)
#define NC     64               // s8 chunks per row (k in [1792,2048))
#define BITS_TILE (WB * 128)    // 7168 u32 per 128-row tile
#define ITERS  8
#define WPI    7                // bit-words per iter
// smem (u32 units): bitsA [0,7168) bitsB [7168,14336) ring [14336, 14336+3*2048) km [20480]
#define SM_RING  14336
#define SM_KM    20480
#define GEMM_SMEM 82048          // bytes (80KB + pad) -> 2 CTAs/SM

__device__ __align__(128) uint32_t g_Abits[(size_t)(BDIM / 128) * BITS_TILE];
__device__ __align__(128) uint32_t g_Bbits[(size_t)(NUNITS / 128) * BITS_TILE];
__device__ __align__(128) uint32_t g_A8[(size_t)(BDIM / 128) * NC * 128];    // [mtile][c][r]
__device__ __align__(128) uint32_t g_B8[(size_t)(NUNITS / 128) * NC * 128];  // [ntile][c][n]

// ============================ PTX helpers ============================

__device__ __forceinline__ uint32_t smem_u32(const void* p) {
    uint32_t a;
    asm("{ .reg .u64 t; cvta.to.shared.u64 t, %1; cvt.u32.u64 %0, t; }" : "=r"(a) : "l"(p));
    return a;
}
__device__ __forceinline__ void cp_async16(uint32_t dst, const void* src) {
    asm volatile("cp.async.cg.shared.global [%0], [%1], 16;" :: "r"(dst), "l"(src) : "memory");
}
#define CP_COMMIT() asm volatile("cp.async.commit_group;" ::: "memory")
#define CP_WAIT(n)  asm volatile("cp.async.wait_group %0;" :: "n"(n) : "memory")

// ============================ Pack kernels ============================

// warp covers row m = warp>>3, words j0=(warp&7)*8 .. +7
__global__ void pack_a(const float* __restrict__ in,
                       uint32_t* __restrict__ bits, uint32_t* __restrict__ a8) {
    int lane = threadIdx.x & 31;
    int warp = (blockIdx.x * blockDim.x + threadIdx.x) >> 5;
    int m  = warp >> 3;
    int j0 = (warp & 7) * 8;
    float v[8];
#pragma unroll
    for (int s = 0; s < 8; s++)
        v[s] = in[(size_t)m * DDIM + (j0 + s) * 32 + lane];
    if (j0 < WB) {
#pragma unroll
        for (int s = 0; s < 8; s++) {
            uint32_t word = __ballot_sync(0xFFFFFFFFu, v[s] < 0.0f);
            if (lane == 0)
                bits[(size_t)(m >> 7) * BITS_TILE + (j0 + s) * 128 + (m & 127)] = word;
        }
    } else {  // j0 == 56: s8 bytes into [mtile][c][r] layout
        uint8_t* a8b = (uint8_t*)a8;
#pragma unroll
        for (int s = 0; s < 8; s++) {
            int c = s * 8 + (lane >> 2);            // chunk within [0,64)
            int kb = lane & 3;
            uint8_t byte = (v[s] < 0.0f) ? 0xFFu : 0x01u;
            a8b[(((size_t)(m >> 7) * NC + c) * 128 + (m & 127)) * 4 + kb] = byte;
        }
    }
}

__global__ void pack_b(const float* __restrict__ kern,
                       uint32_t* __restrict__ bits, uint32_t* __restrict__ b8) {
    __shared__ uint8_t tile[32][33];          // [k][n], 1 = negative
    int n0 = blockIdx.x * 32;
    int k0 = blockIdx.y * 32;
    int tx = threadIdx.x, ty = threadIdx.y;   // (32, 8)
#pragma unroll
    for (int s = 0; s < 4; s++) {
        int kk = ty + s * 8;
        float v = kern[(size_t)(k0 + kk) * NUNITS + n0 + tx];
        tile[kk][tx] = (v < 0.0f) ? 1 : 0;
    }
    __syncthreads();
    int tid = ty * 32 + tx;
    if (blockIdx.y < WB) {
        int wid5 = tid >> 5;
        int lane = tx;
#pragma unroll
        for (int s = 0; s < 4; s++) {
            int nl = wid5 * 4 + s;
            uint32_t word = __ballot_sync(0xFFFFFFFFu, tile[lane][nl] != 0);
            if (lane == 0) {
                int n = n0 + nl;
                bits[(size_t)(n >> 7) * BITS_TILE + blockIdx.y * 128 + (n & 127)] = word;
            }
        }
    } else {  // s8 into [ntile][c][n]
        int nloc = tid & 31;
        int kgrp = tid >> 5;                  // 0..7
        uint32_t w = 0;
#pragma unroll
        for (int b = 0; b < 4; b++) {
            uint32_t byte = tile[kgrp * 4 + b][nloc] ? 0xFFu : 0x01u;
            w |= byte << (8 * b);
        }
        int n = n0 + nloc;
        int c = (blockIdx.y - WB) * 8 + kgrp;
        b8[((size_t)(n >> 7) * NC + c) * 128 + (n & 127)] = w;
    }
}

// ============================ popc + dp4a GEMM ============================
// out[m][n] = 1792 - 2*P + D + bias ;  acc = -2P + D (IMAD opaque -2, dp4a)

__global__ void __launch_bounds__(256, 2) popc_dp4a_gemm(
    const uint32_t* __restrict__ Ab, const uint32_t* __restrict__ Bb,
    const uint32_t* __restrict__ A8, const uint32_t* __restrict__ B8,
    const float* __restrict__ bias, float* __restrict__ out)
{
    extern __shared__ uint32_t sm[];
    const int tid = threadIdx.x;
    const int nblk = blockIdx.x, mblk = blockIdx.y;
    uint32_t* bitsA = sm;
    uint32_t* bitsB = sm + BITS_TILE;
    uint32_t* ring  = sm + SM_RING;
    int* ksm = (int*)(sm + SM_KM);

    if (tid == 0) ksm[0] = -2;

    // one-shot bits copy: 1792 uint4 each
    {
        const uint4* gA = (const uint4*)(Ab + (size_t)mblk * BITS_TILE);
        const uint4* gB = (const uint4*)(Bb + (size_t)nblk * BITS_TILE);
        uint4* sA = (uint4*)bitsA;
        uint4* sB = (uint4*)bitsB;
#pragma unroll
        for (int i = 0; i < 7; i++) {
            sA[tid + i * 256] = gA[tid + i * 256];
            sB[tid + i * 256] = gB[tid + i * 256];
        }
    }

    const uint32_t ring_b = smem_u32(ring);
    const char* gA8 = (const char*)(A8 + (size_t)mblk * (NC * 128));
    const char* gB8 = (const char*)(B8 + (size_t)nblk * (NC * 128));

    // prologue: s8 stages 0,1 (each stage: A 4KB + B 4KB, 1 cp.async16/thread each)
#pragma unroll
    for (int st = 0; st < 2; st++) {
        cp_async16(ring_b + st * 8192 + tid * 16,        gA8 + st * 4096 + tid * 16);
        cp_async16(ring_b + st * 8192 + 4096 + tid * 16, gB8 + st * 4096 + tid * 16);
        CP_COMMIT();
    }
    __syncthreads();
    const int km2 = ksm[0];                   // == -2, opaque -> IMAD on fma pipe
    const int tx = tid & 15, ty = tid >> 4;

    int acc[8][8];
#pragma unroll
    for (int i = 0; i < 8; i++)
#pragma unroll
        for (int k = 0; k < 8; k++) acc[i][k] = 0;

#pragma unroll 1
    for (int it = 0; it < ITERS; it++) {
        __syncthreads();                      // everyone done with the slot being overwritten
        if (it < ITERS - 2) {
            int st = (it + 2) % 3;
            cp_async16(ring_b + st * 8192 + tid * 16,        gA8 + (it + 2) * 4096 + tid * 16);
            cp_async16(ring_b + st * 8192 + 4096 + tid * 16, gB8 + (it + 2) * 4096 + tid * 16);
        }
        CP_COMMIT();
        CP_WAIT(2);
        __syncthreads();

        const uint32_t* stA = ring + (it % 3) * 2048;
        const uint32_t* stB = stA + 1024;

#pragma unroll 1
        for (int s = 0; s < WPI; s++) {       // 7 sub-blocks: 1 bit-word + 1 s8 chunk each
            const int w = it * WPI + s;
            uint32_t aw[8], bw[8], ac[8], bc[8];
            *(uint4*)&aw[0] = *(const uint4*)&bitsA[w * 128 + ty * 8];
            *(uint4*)&aw[4] = *(const uint4*)&bitsA[w * 128 + ty * 8 + 4];
            *(uint4*)&bw[0] = *(const uint4*)&bitsB[w * 128 + tx * 8];
            *(uint4*)&bw[4] = *(const uint4*)&bitsB[w * 128 + tx * 8 + 4];
            *(uint4*)&ac[0] = *(const uint4*)&stA[s * 128 + ty * 8];
            *(uint4*)&ac[4] = *(const uint4*)&stA[s * 128 + ty * 8 + 4];
            *(uint4*)&bc[0] = *(const uint4*)&stB[s * 128 + tx * 8];
            *(uint4*)&bc[4] = *(const uint4*)&stB[s * 128 + tx * 8 + 4];
#pragma unroll
            for (int mi = 0; mi < 8; mi++)
#pragma unroll
                for (int ni = 0; ni < 8; ni++) {
                    int p = __popc(aw[mi] ^ bw[ni]);          // alu: XOR + POPC
                    int a = km2 * p + acc[mi][ni];            // fma: IMAD
                    acc[mi][ni] = __dp4a((int)ac[mi], (int)bc[ni], a);  // fma: IDP
                }
        }
        {   // 8th chunk of this stage: dp4a only
            uint32_t ac[8], bc[8];
            *(uint4*)&ac[0] = *(const uint4*)&stA[7 * 128 + ty * 8];
            *(uint4*)&ac[4] = *(const uint4*)&stA[7 * 128 + ty * 8 + 4];
            *(uint4*)&bc[0] = *(const uint4*)&stB[7 * 128 + tx * 8];
            *(uint4*)&bc[4] = *(const uint4*)&stB[7 * 128 + tx * 8 + 4];
#pragma unroll
            for (int mi = 0; mi < 8; mi++)
#pragma unroll
                for (int ni = 0; ni < 8; ni++)
                    acc[mi][ni] = __dp4a((int)ac[mi], (int)bc[ni], acc[mi][ni]);
        }
    }

    // epilogue: out = 1792 + acc + bias
    const int n0 = nblk * 128 + tx * 8;
    float bl[8];
    *(float4*)&bl[0] = *(const float4*)&bias[n0];
    *(float4*)&bl[4] = *(const float4*)&bias[n0 + 4];
#pragma unroll
    for (int i = 0; i < 8; i++) bl[i] += 1792.0f;

#pragma unroll
    for (int mi = 0; mi < 8; mi++) {
        size_t row = (size_t)(mblk * 128 + ty * 8 + mi) * NUNITS + n0;
        float4 v0, v1;
        v0.x = (float)acc[mi][0] + bl[0];
        v0.y = (float)acc[mi][1] + bl[1];
        v0.z = (float)acc[mi][2] + bl[2];
        v0.w = (float)acc[mi][3] + bl[3];
        v1.x = (float)acc[mi][4] + bl[4];
        v1.y = (float)acc[mi][5] + bl[5];
        v1.z = (float)acc[mi][6] + bl[6];
        v1.w = (float)acc[mi][7] + bl[7];
        *(float4*)&out[row]     = v0;
        *(float4*)&out[row + 4] = v1;
    }
}

// ============================ Host ============================

extern "C" void kernel_launch(void* const* d_in, const int* in_sizes, int n_in,
                              void* d_out, int out_size) {
    const float* inputs = (const float*)d_in[0];
    const float* kern   = (const float*)d_in[1];
    const float* bias   = (const float*)d_in[2];
    float* out = (float*)d_out;

    void *pAb = nullptr, *pBb = nullptr, *pA8 = nullptr, *pB8 = nullptr;
    cudaGetSymbolAddress(&pAb, g_Abits);
    cudaGetSymbolAddress(&pBb, g_Bbits);
    cudaGetSymbolAddress(&pA8, g_A8);
    cudaGetSymbolAddress(&pB8, g_B8);

    // 1) pack A: 8192 rows x 8 warps/row, 8 warps per block
    pack_a<<<BDIM * 8 * 32 / 256, 256>>>(inputs, (uint32_t*)pAb, (uint32_t*)pA8);

    // 2) pack B: one 32x32 tile per block
    {
        dim3 tb(32, 8), tg(NUNITS / 32, DDIM / 32);   // (64, 64)
        pack_b<<<tg, tb>>>(kern, (uint32_t*)pBb, (uint32_t*)pB8);
    }

    // 3) interleaved popc + dp4a GEMM (2 CTAs/SM)
    cudaFuncSetAttribute(popc_dp4a_gemm, cudaFuncAttributeMaxDynamicSharedMemorySize, GEMM_SMEM);
    dim3 grid(NUNITS / 128, BDIM / 128);              // (16, 64)
    popc_dp4a_gemm<<<grid, 256, GEMM_SMEM>>>((const uint32_t*)pAb, (const uint32_t*)pBb,
                                             (const uint32_t*)pA8, (const uint32_t*)pB8,
                                             bias, out);
}

// round 11
// speedup vs baseline: 1.5272x; 1.1286x over previous
#include <cuda_runtime.h>
#include <cstdint>

// Problem shape
#define BDIM   8192
#define DDIM   2048
#define NUNITS 2048
#define KW     64          // 2048 bits = 64 u32 words per row

// Packed sign bits, tiled: [tile][j][rowInTile]. Bit order within words is
// permuted (k = 128*seg + 4*lane + q  ->  word j = 4*seg + q, bit lane) —
// identical permutation for A and B, so XOR+POPC results are unchanged.
__device__ __align__(128) uint32_t g_Abits[(size_t)(BDIM / 128) * KW * 128];   // 2 MB
__device__ __align__(128) uint32_t g_Bbits[(size_t)(NUNITS / 128) * KW * 128]; // 512 KB

// ============================ Pack kernels ============================

// warp w: row m = w>>2, segs (w&3)*4 .. +3 ; each seg = 128 k-values = one float4/lane
__global__ void pack_a_kernel(const float* __restrict__ in, uint32_t* __restrict__ bits) {
    int lane = threadIdx.x & 31;
    int warp = (blockIdx.x * blockDim.x + threadIdx.x) >> 5;
    int m   = warp >> 2;
    int sg0 = (warp & 3) * 4;

    float4 v[4];
#pragma unroll
    for (int s = 0; s < 4; s++)
        v[s] = *(const float4*)&in[(size_t)m * DDIM + (sg0 + s) * 128 + lane * 4];

    uint32_t* base = bits + (size_t)(m >> 7) * (KW * 128) + (m & 127);
#pragma unroll
    for (int s = 0; s < 4; s++) {
        int j0 = (sg0 + s) * 4;
        uint32_t w0 = __ballot_sync(0xFFFFFFFFu, v[s].x < 0.0f);
        uint32_t w1 = __ballot_sync(0xFFFFFFFFu, v[s].y < 0.0f);
        uint32_t w2 = __ballot_sync(0xFFFFFFFFu, v[s].z < 0.0f);
        uint32_t w3 = __ballot_sync(0xFFFFFFFFu, v[s].w < 0.0f);
        if (lane == 0) {
            base[(j0 + 0) * 128] = w0;
            base[(j0 + 1) * 128] = w1;
            base[(j0 + 2) * 128] = w2;
            base[(j0 + 3) * 128] = w3;
        }
    }
}

// block: 128 k-rows x 32 n-cols. Same permutation as pack_a:
// word j = 4*blockIdx.y + q, bit l = sign(kern[128*by + 4l + q][n])
__global__ void pack_b_kernel(const float* __restrict__ kern, uint32_t* __restrict__ bits) {
    __shared__ uint8_t tile[128 * 33];        // [k][n], padded row 33 -> conflict-free
    int n0 = blockIdx.x * 32;
    int kb = blockIdx.y * 128;
    int tx = threadIdx.x, ty = threadIdx.y;   // (32, 8)
#pragma unroll
    for (int s = 0; s < 16; s++) {
        int k = ty + s * 8;
        float v = kern[(size_t)(kb + k) * NUNITS + n0 + tx];
        tile[k * 33 + tx] = (v < 0.0f) ? 1 : 0;
    }
    __syncthreads();

    int lane = tx;                            // warp = ty
#pragma unroll
    for (int nl = 0; nl < 4; nl++) {
        int n = n0 + ty * 4 + nl;
        uint32_t* dst = bits + (size_t)(n >> 7) * (KW * 128) + (n & 127);
#pragma unroll
        for (int q = 0; q < 4; q++) {
            uint8_t val = tile[(4 * lane + q) * 33 + (ty * 4 + nl)];
            uint32_t word = __ballot_sync(0xFFFFFFFFu, val != 0);
            if (lane == 0)
                dst[(blockIdx.y * 4 + q) * 128] = word;
        }
    }
}

// ============================ popcount GEMM ============================
// out[m][n] = 2048 - 2 * sum_j popc(A[m][j] ^ B[n][j]) + bias[n]
// 3:2 CSA on word triples; accumulation via IMAD with smem-opaque multipliers
// so the adds issue on the (idle) fma pipe instead of the saturated alu port.

__global__ void __launch_bounds__(256, 2) popc_gemm(
    const uint32_t* __restrict__ Ab, const uint32_t* __restrict__ Bb,
    const float* __restrict__ bias, float* __restrict__ out)
{
    extern __shared__ uint32_t smem[];        // A 8192 words, B 8192 words, k1/k2
    uint32_t* Asm = smem;
    uint32_t* Bsm = smem + KW * 128;
    int* ksm = (int*)(smem + 2 * KW * 128);

    const int tid = threadIdx.x;
    const int nblk = blockIdx.x, mblk = blockIdx.y;

    if (tid == 0) { ksm[0] = 1; ksm[1] = 2; }

    {
        const uint4* gA = (const uint4*)(Ab + (size_t)mblk * (KW * 128));
        const uint4* gB = (const uint4*)(Bb + (size_t)nblk * (KW * 128));
        uint4* sA = (uint4*)Asm;
        uint4* sB = (uint4*)Bsm;
#pragma unroll
        for (int i = 0; i < 8; i++) {
            sA[tid + i * 256] = gA[tid + i * 256];
            sB[tid + i * 256] = gB[tid + i * 256];
        }
    }
    __syncthreads();

    const int k1 = ksm[0];                    // == 1, opaque
    const int k2 = ksm[1];                    // == 2, opaque
    const int tx = tid & 15;
    const int ty = tid >> 4;

    int acc[8][8];
#pragma unroll
    for (int i = 0; i < 8; i++)
#pragma unroll
        for (int k = 0; k < 8; k++) acc[i][k] = 0;

    // 20 CSA triples (words 0..59)
#pragma unroll 2
    for (int jg = 0; jg < 20; jg++) {
        uint32_t a0[8], a1[8], a2[8], b0[8], b1[8], b2[8];
        const uint32_t* Ap = &Asm[(jg * 3) * 128 + ty * 8];
        const uint32_t* Bp = &Bsm[(jg * 3) * 128 + tx * 8];
        *(uint4*)&a0[0] = *(const uint4*)&Ap[0];   *(uint4*)&a0[4] = *(const uint4*)&Ap[4];
        *(uint4*)&a1[0] = *(const uint4*)&Ap[128]; *(uint4*)&a1[4] = *(const uint4*)&Ap[132];
        *(uint4*)&a2[0] = *(const uint4*)&Ap[256]; *(uint4*)&a2[4] = *(const uint4*)&Ap[260];
        *(uint4*)&b0[0] = *(const uint4*)&Bp[0];   *(uint4*)&b0[4] = *(const uint4*)&Bp[4];
        *(uint4*)&b1[0] = *(const uint4*)&Bp[128]; *(uint4*)&b1[4] = *(const uint4*)&Bp[132];
        *(uint4*)&b2[0] = *(const uint4*)&Bp[256]; *(uint4*)&b2[4] = *(const uint4*)&Bp[260];
#pragma unroll
        for (int mi = 0; mi < 8; mi++) {
#pragma unroll
            for (int ni = 0; ni < 8; ni++) {
                uint32_t x0 = a0[mi] ^ b0[ni];
                uint32_t x1 = a1[mi] ^ b1[ni];
                uint32_t x2 = a2[mi] ^ b2[ni];
                uint32_t s = x0 ^ x1 ^ x2;                      // LOP3 0x96
                uint32_t c = (x0 & x1) | (x2 & (x0 | x1));      // LOP3 0xE8
                int a = acc[mi][ni];
                a = __popc(s) * k1 + a;                         // IMAD (fma pipe)
                a = __popc(c) * k2 + a;                         // IMAD (fma pipe)
                acc[mi][ni] = a;
            }
        }
    }
    // raw tail: words 60..63
    {
        uint32_t a0[8], a1[8], a2[8], a3[8], b0[8], b1[8], b2[8], b3[8];
        const uint32_t* Ap = &Asm[60 * 128 + ty * 8];
        const uint32_t* Bp = &Bsm[60 * 128 + tx * 8];
        *(uint4*)&a0[0] = *(const uint4*)&Ap[0];   *(uint4*)&a0[4] = *(const uint4*)&Ap[4];
        *(uint4*)&a1[0] = *(const uint4*)&Ap[128]; *(uint4*)&a1[4] = *(const uint4*)&Ap[132];
        *(uint4*)&a2[0] = *(const uint4*)&Ap[256]; *(uint4*)&a2[4] = *(const uint4*)&Ap[260];
        *(uint4*)&a3[0] = *(const uint4*)&Ap[384]; *(uint4*)&a3[4] = *(const uint4*)&Ap[388];
        *(uint4*)&b0[0] = *(const uint4*)&Bp[0];   *(uint4*)&b0[4] = *(const uint4*)&Bp[4];
        *(uint4*)&b1[0] = *(const uint4*)&Bp[128]; *(uint4*)&b1[4] = *(const uint4*)&Bp[132];
        *(uint4*)&b2[0] = *(const uint4*)&Bp[256]; *(uint4*)&b2[4] = *(const uint4*)&Bp[260];
        *(uint4*)&b3[0] = *(const uint4*)&Bp[384]; *(uint4*)&b3[4] = *(const uint4*)&Bp[388];
#pragma unroll
        for (int mi = 0; mi < 8; mi++) {
#pragma unroll
            for (int ni = 0; ni < 8; ni++) {
                int a = acc[mi][ni];
                a = __popc(a0[mi] ^ b0[ni]) * k1 + a;
                a = __popc(a1[mi] ^ b1[ni]) * k1 + a;
                a = __popc(a2[mi] ^ b2[ni]) * k1 + a;
                a = __popc(a3[mi] ^ b3[ni]) * k1 + a;
                acc[mi][ni] = a;
            }
        }
    }

    // epilogue: val = 2048 - 2*acc + bias
    const int n0 = nblk * 128 + tx * 8;
    float bl[8];
    *(float4*)&bl[0] = *(const float4*)&bias[n0];
    *(float4*)&bl[4] = *(const float4*)&bias[n0 + 4];
#pragma unroll
    for (int i = 0; i < 8; i++) bl[i] += 2048.0f;

#pragma unroll
    for (int mi = 0; mi < 8; mi++) {
        size_t row = (size_t)(mblk * 128 + ty * 8 + mi) * NUNITS + n0;
        float4 v0, v1;
        v0.x = fmaf(-2.0f, (float)acc[mi][0], bl[0]);
        v0.y = fmaf(-2.0f, (float)acc[mi][1], bl[1]);
        v0.z = fmaf(-2.0f, (float)acc[mi][2], bl[2]);
        v0.w = fmaf(-2.0f, (float)acc[mi][3], bl[3]);
        v1.x = fmaf(-2.0f, (float)acc[mi][4], bl[4]);
        v1.y = fmaf(-2.0f, (float)acc[mi][5], bl[5]);
        v1.z = fmaf(-2.0f, (float)acc[mi][6], bl[6]);
        v1.w = fmaf(-2.0f, (float)acc[mi][7], bl[7]);
        *(float4*)&out[row]     = v0;
        *(float4*)&out[row + 4] = v1;
    }
}

// ============================ Host ============================

#define GEMM_SMEM (2 * KW * 128 * 4 + 16)   // 64 KB + k1/k2

extern "C" void kernel_launch(void* const* d_in, const int* in_sizes, int n_in,
                              void* d_out, int out_size) {
    const float* inputs = (const float*)d_in[0];
    const float* kern   = (const float*)d_in[1];
    const float* bias   = (const float*)d_in[2];
    float* out = (float*)d_out;

    void *pA = nullptr, *pB = nullptr;
    cudaGetSymbolAddress(&pA, g_Abits);
    cudaGetSymbolAddress(&pB, g_Bbits);

    // 1) pack A: warp per (row, 4 segs); 8 warps/block
    pack_a_kernel<<<(BDIM * 4) / 8, 256>>>(inputs, (uint32_t*)pA);

    // 2) pack B: 128k x 32n tile per block
    {
        dim3 tb(32, 8), tg(NUNITS / 32, DDIM / 128);   // (64, 16)
        pack_b_kernel<<<tg, tb>>>(kern, (uint32_t*)pB);
    }

    // 3) CSA popcount GEMM, 2 CTAs/SM, IMAD accumulation on fma pipe
    cudaFuncSetAttribute(popc_gemm, cudaFuncAttributeMaxDynamicSharedMemorySize, GEMM_SMEM);
    dim3 grid(NUNITS / 128, BDIM / 128);       // (16, 64)
    popc_gemm<<<grid, 256, GEMM_SMEM>>>((const uint32_t*)pA, (const uint32_t*)pB, bias, out);
}

// round 12
// speedup vs baseline: 1.6373x; 1.0721x over previous
#include <cuda_runtime.h>
#include <cstdint>

// Problem shape
#define BDIM   8192
#define DDIM   2048
#define NUNITS 2048
#define KW     64          // 2048 bits = 64 u32 words per row

// A bits: [128-row tile][j][rowInTile] ; B bits: [64-col tile][j][colInTile]
// Bit order inside words is permuted identically for A and B (XOR/POPC invariant).
__device__ __align__(128) uint32_t g_Abits[(size_t)(BDIM / 128) * KW * 128];   // 2 MB
__device__ __align__(128) uint32_t g_Bbits[(size_t)(NUNITS / 64) * KW * 64];   // 512 KB

// ============================ Pack kernels ============================

// warp w: row m = w>>2, segs (w&3)*4 .. +3 ; each seg = 128 k-values = one float4/lane
__global__ void pack_a_kernel(const float* __restrict__ in, uint32_t* __restrict__ bits) {
    int lane = threadIdx.x & 31;
    int warp = (blockIdx.x * blockDim.x + threadIdx.x) >> 5;
    int m   = warp >> 2;
    int sg0 = (warp & 3) * 4;

    float4 v[4];
#pragma unroll
    for (int s = 0; s < 4; s++)
        v[s] = *(const float4*)&in[(size_t)m * DDIM + (sg0 + s) * 128 + lane * 4];

    uint32_t* base = bits + (size_t)(m >> 7) * (KW * 128) + (m & 127);
#pragma unroll
    for (int s = 0; s < 4; s++) {
        int j0 = (sg0 + s) * 4;
        uint32_t w0 = __ballot_sync(0xFFFFFFFFu, v[s].x < 0.0f);
        uint32_t w1 = __ballot_sync(0xFFFFFFFFu, v[s].y < 0.0f);
        uint32_t w2 = __ballot_sync(0xFFFFFFFFu, v[s].z < 0.0f);
        uint32_t w3 = __ballot_sync(0xFFFFFFFFu, v[s].w < 0.0f);
        if (lane == 0) {
            base[(j0 + 0) * 128] = w0;
            base[(j0 + 1) * 128] = w1;
            base[(j0 + 2) * 128] = w2;
            base[(j0 + 3) * 128] = w3;
        }
    }
}

// block: 128 k-rows x 32 n-cols. word j = 4*blockIdx.y + q, bit l = sign(kern[128*by+4l+q][n])
__global__ void pack_b_kernel(const float* __restrict__ kern, uint32_t* __restrict__ bits) {
    __shared__ uint8_t tile[128 * 33];        // [k][n], padded -> conflict-free
    int n0 = blockIdx.x * 32;
    int kb = blockIdx.y * 128;
    int tx = threadIdx.x, ty = threadIdx.y;   // (32, 8)
#pragma unroll
    for (int s = 0; s < 16; s++) {
        int k = ty + s * 8;
        float v = kern[(size_t)(kb + k) * NUNITS + n0 + tx];
        tile[k * 33 + tx] = (v < 0.0f) ? 1 : 0;
    }
    __syncthreads();

    int lane = tx;                            // warp = ty
#pragma unroll
    for (int nl = 0; nl < 4; nl++) {
        int n = n0 + ty * 4 + nl;
        uint32_t* dst = bits + (size_t)(n >> 6) * (KW * 64) + (n & 63);
#pragma unroll
        for (int q = 0; q < 4; q++) {
            uint8_t val = tile[(4 * lane + q) * 33 + (ty * 4 + nl)];
            uint32_t word = __ballot_sync(0xFFFFFFFFu, val != 0);
            if (lane == 0)
                dst[(blockIdx.y * 4 + q) * 64] = word;
        }
    }
}

// ============================ popcount GEMM (128x64 tiles) ============================
// out[m][n] = 2048 - 2 * sum_j popc(A[m][j] ^ B[n][j]) + bias[n]
// 2048 CTAs -> 6.92 tiles per resident slot -> 1.2% wave tail (was 13.5% at 1024).

__global__ void __launch_bounds__(256, 2) popc_gemm(
    const uint32_t* __restrict__ Ab, const uint32_t* __restrict__ Bb,
    const float* __restrict__ bias, float* __restrict__ out)
{
    extern __shared__ uint32_t smem[];        // A 8192 words, B 4096 words, k1/k2
    uint32_t* Asm = smem;
    uint32_t* Bsm = smem + KW * 128;
    int* ksm = (int*)(smem + KW * 128 + KW * 64);

    const int tid = threadIdx.x;
    const int nblk = blockIdx.x, mblk = blockIdx.y;

    if (tid == 0) { ksm[0] = 1; ksm[1] = 2; }

    {
        const uint4* gA = (const uint4*)(Ab + (size_t)mblk * (KW * 128));
        uint4* sA = (uint4*)Asm;
#pragma unroll
        for (int i = 0; i < 8; i++)
            sA[tid + i * 256] = gA[tid + i * 256];
        const uint4* gB = (const uint4*)(Bb + (size_t)nblk * (KW * 64));
        uint4* sB = (uint4*)Bsm;
#pragma unroll
        for (int i = 0; i < 4; i++)
            sB[tid + i * 256] = gB[tid + i * 256];
    }
    __syncthreads();

    const int k1 = ksm[0];                    // == 1, opaque -> IMAD on fma pipe
    const int k2 = ksm[1];                    // == 2, opaque
    const int tx = tid & 15;                  // 16 n-subblocks x 4 cols
    const int ty = tid >> 4;                  // 16 m-subblocks x 8 rows

    int acc[8][4];
#pragma unroll
    for (int i = 0; i < 8; i++)
#pragma unroll
        for (int k = 0; k < 4; k++) acc[i][k] = 0;

    // 20 CSA triples (words 0..59)
#pragma unroll 2
    for (int jg = 0; jg < 20; jg++) {
        uint32_t a0[8], a1[8], a2[8], b0[4], b1[4], b2[4];
        const uint32_t* Ap = &Asm[(jg * 3) * 128 + ty * 8];
        const uint32_t* Bp = &Bsm[(jg * 3) * 64 + tx * 4];
        *(uint4*)&a0[0] = *(const uint4*)&Ap[0];   *(uint4*)&a0[4] = *(const uint4*)&Ap[4];
        *(uint4*)&a1[0] = *(const uint4*)&Ap[128]; *(uint4*)&a1[4] = *(const uint4*)&Ap[132];
        *(uint4*)&a2[0] = *(const uint4*)&Ap[256]; *(uint4*)&a2[4] = *(const uint4*)&Ap[260];
        *(uint4*)&b0[0] = *(const uint4*)&Bp[0];
        *(uint4*)&b1[0] = *(const uint4*)&Bp[64];
        *(uint4*)&b2[0] = *(const uint4*)&Bp[128];
#pragma unroll
        for (int mi = 0; mi < 8; mi++) {
#pragma unroll
            for (int ni = 0; ni < 4; ni++) {
                uint32_t x0 = a0[mi] ^ b0[ni];
                uint32_t x1 = a1[mi] ^ b1[ni];
                uint32_t x2 = a2[mi] ^ b2[ni];
                uint32_t s = x0 ^ x1 ^ x2;                      // LOP3 0x96
                uint32_t c = (x0 & x1) | (x2 & (x0 | x1));      // LOP3 0xE8
                int a = acc[mi][ni];
                a = __popc(s) * k1 + a;                         // IMAD (fma pipe)
                a = __popc(c) * k2 + a;                         // IMAD (fma pipe)
                acc[mi][ni] = a;
            }
        }
    }
    // raw tail: words 60..63
    {
        uint32_t a0[8], a1[8], a2[8], a3[8], b0[4], b1[4], b2[4], b3[4];
        const uint32_t* Ap = &Asm[60 * 128 + ty * 8];
        const uint32_t* Bp = &Bsm[60 * 64 + tx * 4];
        *(uint4*)&a0[0] = *(const uint4*)&Ap[0];   *(uint4*)&a0[4] = *(const uint4*)&Ap[4];
        *(uint4*)&a1[0] = *(const uint4*)&Ap[128]; *(uint4*)&a1[4] = *(const uint4*)&Ap[132];
        *(uint4*)&a2[0] = *(const uint4*)&Ap[256]; *(uint4*)&a2[4] = *(const uint4*)&Ap[260];
        *(uint4*)&a3[0] = *(const uint4*)&Ap[384]; *(uint4*)&a3[4] = *(const uint4*)&Ap[388];
        *(uint4*)&b0[0] = *(const uint4*)&Bp[0];
        *(uint4*)&b1[0] = *(const uint4*)&Bp[64];
        *(uint4*)&b2[0] = *(const uint4*)&Bp[128];
        *(uint4*)&b3[0] = *(const uint4*)&Bp[192];
#pragma unroll
        for (int mi = 0; mi < 8; mi++) {
#pragma unroll
            for (int ni = 0; ni < 4; ni++) {
                int a = acc[mi][ni];
                a = __popc(a0[mi] ^ b0[ni]) * k1 + a;
                a = __popc(a1[mi] ^ b1[ni]) * k1 + a;
                a = __popc(a2[mi] ^ b2[ni]) * k1 + a;
                a = __popc(a3[mi] ^ b3[ni]) * k1 + a;
                acc[mi][ni] = a;
            }
        }
    }

    // epilogue: val = 2048 - 2*acc + bias
    const int n0 = nblk * 64 + tx * 4;
    float bl[4];
    *(float4*)&bl[0] = *(const float4*)&bias[n0];
#pragma unroll
    for (int i = 0; i < 4; i++) bl[i] += 2048.0f;

#pragma unroll
    for (int mi = 0; mi < 8; mi++) {
        size_t row = (size_t)(mblk * 128 + ty * 8 + mi) * NUNITS + n0;
        float4 v0;
        v0.x = fmaf(-2.0f, (float)acc[mi][0], bl[0]);
        v0.y = fmaf(-2.0f, (float)acc[mi][1], bl[1]);
        v0.z = fmaf(-2.0f, (float)acc[mi][2], bl[2]);
        v0.w = fmaf(-2.0f, (float)acc[mi][3], bl[3]);
        *(float4*)&out[row] = v0;
    }
}

// ============================ Host ============================

#define GEMM_SMEM ((KW * 128 + KW * 64) * 4 + 16)   // 48 KB + k1/k2 -> 2 CTAs/SM

extern "C" void kernel_launch(void* const* d_in, const int* in_sizes, int n_in,
                              void* d_out, int out_size) {
    const float* inputs = (const float*)d_in[0];
    const float* kern   = (const float*)d_in[1];
    const float* bias   = (const float*)d_in[2];
    float* out = (float*)d_out;

    void *pA = nullptr, *pB = nullptr;
    cudaGetSymbolAddress(&pA, g_Abits);
    cudaGetSymbolAddress(&pB, g_Bbits);

    // 1) pack A: warp per (row, 4 segs); 8 warps/block
    pack_a_kernel<<<(BDIM * 4) / 8, 256>>>(inputs, (uint32_t*)pA);

    // 2) pack B: 128k x 32n tile per block
    {
        dim3 tb(32, 8), tg(NUNITS / 32, DDIM / 128);   // (64, 16)
        pack_b_kernel<<<tg, tb>>>(kern, (uint32_t*)pB);
    }

    // 3) CSA popcount GEMM, 128x64 tiles, 2 CTAs/SM
    cudaFuncSetAttribute(popc_gemm, cudaFuncAttributeMaxDynamicSharedMemorySize, GEMM_SMEM);
    dim3 grid(NUNITS / 64, BDIM / 128);        // (32, 64) = 2048 CTAs
    popc_gemm<<<grid, 256, GEMM_SMEM>>>((const uint32_t*)pA, (const uint32_t*)pB, bias, out);
}